// round 1
// baseline (speedup 1.0000x reference)
#include <cuda_runtime.h>
#include <math.h>

// ---------------------------------------------------------------------------
// Problem-size capacities (reference: N=50000, E=800000; runtime values are
// read from in_sizes but must not exceed these).
// ---------------------------------------------------------------------------
#define MAXN 50048
#define MAXE 800000

// Scratch (device globals -- no allocation allowed)
__device__ __align__(128) float g_h[MAXN * 256];
__device__ __align__(128) float g_skip[MAXN * 256];
__device__ __align__(128) float g_hw[MAXN * 256];
__device__ __align__(128) float g_p[MAXN * 256];
__device__ __align__(128) float g_agg[MAXN * 256];
__device__ __align__(128) float g_f1[MAXN * 512];
__device__ __align__(128) float g_logits[MAXN * 64];
__device__ __align__(128) float g_deg[MAXN];
__device__ __align__(128) float g_dinv[MAXN];
__device__ __align__(128) float g_norm[MAXE];

// ---------------------------------------------------------------------------
// Small helpers
// ---------------------------------------------------------------------------
__device__ __forceinline__ float gelu_exact(float x) {
    return 0.5f * x * (1.0f + erff(x * 0.70710678118654752440f));
}

__global__ void k_fill1(float* p, int n) {
    int i = blockIdx.x * blockDim.x + threadIdx.x;
    if (i < n) p[i] = 1.0f;
}

__global__ void k_deg_acc(float* deg, const int* __restrict__ dst, int e) {
    int i = blockIdx.x * blockDim.x + threadIdx.x;
    if (i < e) atomicAdd(&deg[dst[i]], 1.0f);
}

__global__ void k_dinv(float* __restrict__ dinv, const float* __restrict__ deg, int n) {
    int i = blockIdx.x * blockDim.x + threadIdx.x;
    if (i < n) dinv[i] = rsqrtf(deg[i]);
}

__global__ void k_norm(float* __restrict__ norm, const float* __restrict__ dinv,
                       const int* __restrict__ src, const int* __restrict__ dst, int e) {
    int i = blockIdx.x * blockDim.x + threadIdx.x;
    if (i < e) norm[i] = dinv[src[i]] * dinv[dst[i]];
}

// ---------------------------------------------------------------------------
// SGEMM: C[M,Ncols] = A[M,K] @ B[K,Ncols]
// 64x64 tile, BK=16, 256 threads, 4x4 outputs/thread.
// K % 16 == 0, Ncols % 64 == 0 (true here: K in {128,256,512}, Ncols in {256,512,64}).
// Row dimension (M) is bounds-checked.
// ---------------------------------------------------------------------------
__global__ void sgemm(const float* __restrict__ A, const float* __restrict__ B,
                      float* __restrict__ C, int M, int K, int Ncols) {
    __shared__ float As[16][64];
    __shared__ float Bs[16][64];
    int tid  = threadIdx.x;
    int row0 = blockIdx.y * 64;
    int col0 = blockIdx.x * 64;
    int tx = tid & 15, ty = tid >> 4;

    int ar = tid >> 2, ak = (tid & 3) * 4;   // A tile load: row 0..63, 4 k's
    int bk = tid >> 4, bc = (tid & 15) * 4;  // B tile load: k 0..15, 4 cols

    float acc[4][4];
    #pragma unroll
    for (int i = 0; i < 4; i++)
        #pragma unroll
        for (int j = 0; j < 4; j++) acc[i][j] = 0.0f;

    for (int k0 = 0; k0 < K; k0 += 16) {
        float4 av = make_float4(0.f, 0.f, 0.f, 0.f);
        if (row0 + ar < M)
            av = *(const float4*)&A[(size_t)(row0 + ar) * K + k0 + ak];
        As[ak + 0][ar] = av.x;
        As[ak + 1][ar] = av.y;
        As[ak + 2][ar] = av.z;
        As[ak + 3][ar] = av.w;

        float4 bv = *(const float4*)&B[(size_t)(k0 + bk) * Ncols + col0 + bc];
        *(float4*)&Bs[bk][bc] = bv;
        __syncthreads();

        #pragma unroll
        for (int k = 0; k < 16; k++) {
            float a[4], b[4];
            #pragma unroll
            for (int i = 0; i < 4; i++) a[i] = As[k][ty * 4 + i];
            #pragma unroll
            for (int j = 0; j < 4; j++) b[j] = Bs[k][tx * 4 + j];
            #pragma unroll
            for (int i = 0; i < 4; i++)
                #pragma unroll
                for (int j = 0; j < 4; j++) acc[i][j] += a[i] * b[j];
        }
        __syncthreads();
    }

    #pragma unroll
    for (int i = 0; i < 4; i++) {
        int r = row0 + ty * 4 + i;
        if (r < M) {
            float4 o = make_float4(acc[i][0], acc[i][1], acc[i][2], acc[i][3]);
            *(float4*)&C[(size_t)r * Ncols + col0 + tx * 4] = o;
        }
    }
}

// ---------------------------------------------------------------------------
// Edge scatter: agg[dst] += hw[src] * norm  (256-wide rows, float4 chunks)
// One thread per (edge, 16B chunk): 64 chunk-threads per edge.
// Uses vector red.global.add.v4.f32 (sm_90+) to quarter the atomic count.
// ---------------------------------------------------------------------------
__global__ void scatter_add(const float* __restrict__ hw, float* __restrict__ agg,
                            const int* __restrict__ src, const int* __restrict__ dst,
                            const float* __restrict__ norm, int E) {
    long long t = (long long)blockIdx.x * blockDim.x + threadIdx.x;
    int e = (int)(t >> 6);
    int c = (int)(t & 63);
    if (e >= E) return;
    int s = src[e], d = dst[e];
    float w = norm[e];
    float4 v = *(const float4*)&hw[(size_t)s * 256 + c * 4];
    float* p = &agg[(size_t)d * 256 + c * 4];
#if __CUDA_ARCH__ >= 900
    asm volatile("red.global.add.v4.f32 [%0], {%1,%2,%3,%4};"
                 :: "l"(p), "f"(v.x * w), "f"(v.y * w), "f"(v.z * w), "f"(v.w * w)
                 : "memory");
#else
    atomicAdd(p + 0, v.x * w);
    atomicAdd(p + 1, v.y * w);
    atomicAdd(p + 2, v.z * w);
    atomicAdd(p + 3, v.w * w);
#endif
}

// ---------------------------------------------------------------------------
// Per-layer epilogue: t = agg + dinv^2*hw + bc + p + bp ; skip = t ;
// h = gelu(layer_norm(t) * g + be).   One block (256 thr) per row; C = 256.
// ---------------------------------------------------------------------------
__global__ void post_layer(const float* __restrict__ agg, const float* __restrict__ hw,
                           const float* __restrict__ pp, const float* __restrict__ dinv,
                           const float* __restrict__ bcv, const float* __restrict__ bpv,
                           const float* __restrict__ gv, const float* __restrict__ bev,
                           float* __restrict__ skip_out, float* __restrict__ h_out) {
    int r = blockIdx.x;
    int c = threadIdx.x;
    size_t idx = (size_t)r * 256 + c;
    float di = dinv[r];
    float t = agg[idx] + di * di * hw[idx] + bcv[c] + pp[idx] + bpv[c];
    skip_out[idx] = t;

    __shared__ float red[8];
    float s = t;
    #pragma unroll
    for (int o = 16; o > 0; o >>= 1) s += __shfl_xor_sync(0xffffffffu, s, o);
    if ((c & 31) == 0) red[c >> 5] = s;
    __syncthreads();
    float m = 0.f;
    #pragma unroll
    for (int i = 0; i < 8; i++) m += red[i];
    m *= (1.0f / 256.0f);
    __syncthreads();

    float d = t - m;
    float sq = d * d;
    #pragma unroll
    for (int o = 16; o > 0; o >>= 1) sq += __shfl_xor_sync(0xffffffffu, sq, o);
    if ((c & 31) == 0) red[c >> 5] = sq;
    __syncthreads();
    float v = 0.f;
    #pragma unroll
    for (int i = 0; i < 8; i++) v += red[i];
    v *= (1.0f / 256.0f);

    float y = d * rsqrtf(v + 1e-5f) * gv[c] + bev[c];
    h_out[idx] = gelu_exact(y);
}

// h = p + b_in[col] + h  (long residual), 256 cols
__global__ void k_resid(float* __restrict__ h, const float* __restrict__ p,
                        const float* __restrict__ b_in, int total) {
    int i = blockIdx.x * blockDim.x + threadIdx.x;
    if (i < total) {
        int c = i & 255;
        h[i] = p[i] + b_in[c] + h[i];
    }
}

// f1 = gelu(f1 + bf1[col]), 512 cols
__global__ void k_biasgelu(float* __restrict__ f, const float* __restrict__ b, int total) {
    int i = blockIdx.x * blockDim.x + threadIdx.x;
    if (i < total) {
        int c = i & 511;
        f[i] = gelu_exact(f[i] + b[c]);
    }
}

// log_softmax over 64 logits per row; warp per row, lane handles 2 cols.
__global__ void k_logsoftmax(const float* __restrict__ logits, const float* __restrict__ bf2,
                             float* __restrict__ out, int Nn) {
    int r = blockIdx.x * 8 + (threadIdx.x >> 5);
    int lane = threadIdx.x & 31;
    if (r >= Nn) return;
    float v0 = logits[(size_t)r * 64 + lane]      + bf2[lane];
    float v1 = logits[(size_t)r * 64 + 32 + lane] + bf2[32 + lane];
    float mx = fmaxf(v0, v1);
    #pragma unroll
    for (int o = 16; o > 0; o >>= 1) mx = fmaxf(mx, __shfl_xor_sync(0xffffffffu, mx, o));
    float s = expf(v0 - mx) + expf(v1 - mx);
    #pragma unroll
    for (int o = 16; o > 0; o >>= 1) s += __shfl_xor_sync(0xffffffffu, s, o);
    float ls = logf(s);
    out[(size_t)r * 64 + lane]      = v0 - mx - ls;
    out[(size_t)r * 64 + 32 + lane] = v1 - mx - ls;
}

// ---------------------------------------------------------------------------
// Launch
// ---------------------------------------------------------------------------
extern "C" void kernel_launch(void* const* d_in, const int* in_sizes, int n_in,
                              void* d_out, int out_size) {
    const float* x   = (const float*)d_in[0];
    const int*   ei  = (const int*)d_in[1];
    int E  = in_sizes[1] / 2;
    int Nn = in_sizes[0] / 128;
    const int* src = ei;
    const int* dst = ei + E;

    const float* Wc[3] = {(const float*)d_in[2],  (const float*)d_in[8],  (const float*)d_in[14]};
    const float* bc[3] = {(const float*)d_in[3],  (const float*)d_in[9],  (const float*)d_in[15]};
    const float* Wp[3] = {(const float*)d_in[4],  (const float*)d_in[10], (const float*)d_in[16]};
    const float* bp[3] = {(const float*)d_in[5],  (const float*)d_in[11], (const float*)d_in[17]};
    const float* gg[3] = {(const float*)d_in[6],  (const float*)d_in[12], (const float*)d_in[18]};
    const float* be[3] = {(const float*)d_in[7],  (const float*)d_in[13], (const float*)d_in[19]};
    const float* W_in = (const float*)d_in[20];
    const float* b_in = (const float*)d_in[21];
    const float* Wf1  = (const float*)d_in[22];
    const float* bf1  = (const float*)d_in[23];
    const float* Wf2  = (const float*)d_in[24];
    const float* bf2  = (const float*)d_in[25];
    float* out = (float*)d_out;

    float *pH, *pSkip, *pHw, *pP, *pAgg, *pF1, *pLog, *pDeg, *pDinv, *pNorm;
    cudaGetSymbolAddress((void**)&pH,    g_h);
    cudaGetSymbolAddress((void**)&pSkip, g_skip);
    cudaGetSymbolAddress((void**)&pHw,   g_hw);
    cudaGetSymbolAddress((void**)&pP,    g_p);
    cudaGetSymbolAddress((void**)&pAgg,  g_agg);
    cudaGetSymbolAddress((void**)&pF1,   g_f1);
    cudaGetSymbolAddress((void**)&pLog,  g_logits);
    cudaGetSymbolAddress((void**)&pDeg,  g_deg);
    cudaGetSymbolAddress((void**)&pDinv, g_dinv);
    cudaGetSymbolAddress((void**)&pNorm, g_norm);

    // --- degree / normalization ---
    k_fill1  <<<(Nn + 255) / 256, 256>>>(pDeg, Nn);
    k_deg_acc<<<(E  + 255) / 256, 256>>>(pDeg, dst, E);
    k_dinv   <<<(Nn + 255) / 256, 256>>>(pDinv, pDeg, Nn);
    k_norm   <<<(E  + 255) / 256, 256>>>(pNorm, pDinv, src, dst, E);

    // --- 3 GCN layers ---
    const float* h    = x;
    const float* skip = x;
    int Kin = 128;
    int gy = (Nn + 63) / 64;
    for (int l = 0; l < 3; l++) {
        sgemm<<<dim3(4, gy), 256>>>(h,    Wc[l], pHw, Nn, Kin, 256);
        sgemm<<<dim3(4, gy), 256>>>(skip, Wp[l], pP,  Nn, Kin, 256);
        cudaMemsetAsync(pAgg, 0, (size_t)Nn * 256 * sizeof(float), 0);
        {
            long long work = (long long)E * 64;
            int blocks = (int)((work + 255) / 256);
            scatter_add<<<blocks, 256>>>(pHw, pAgg, src, dst, pNorm, E);
        }
        post_layer<<<Nn, 256>>>(pAgg, pHw, pP, pDinv, bc[l], bp[l], gg[l], be[l], pSkip, pH);
        h = pH; skip = pSkip; Kin = 256;
    }

    // --- long residual + MLP head ---
    sgemm<<<dim3(4, gy), 256>>>(x, W_in, pP, Nn, 128, 256);
    k_resid<<<((Nn * 256) + 255) / 256, 256>>>(pH, pP, b_in, Nn * 256);

    sgemm<<<dim3(8, gy), 256>>>(pH, Wf1, pF1, Nn, 256, 512);
    k_biasgelu<<<((Nn * 512) + 255) / 256, 256>>>(pF1, bf1, Nn * 512);

    sgemm<<<dim3(1, gy), 256>>>(pF1, Wf2, pLog, Nn, 512, 64);
    k_logsoftmax<<<(Nn + 7) / 8, 256>>>(pLog, bf2, out, Nn);
}

// round 2
// speedup vs baseline: 2.0522x; 2.0522x over previous
#include <cuda_runtime.h>
#include <math.h>
#include <stdint.h>

#define MAXN 50048
#define MAXE 800000

// ---------------- scratch (device globals; no allocation allowed) ----------
__device__ __align__(128) float g_h[MAXN * 256];
__device__ __align__(128) float g_skip[MAXN * 256];
__device__ __align__(128) float g_hw[MAXN * 256];
__device__ __align__(128) float g_p[MAXN * 256];
__device__ __align__(128) float g_f1[MAXN * 512];
__device__ __align__(128) float g_logits[MAXN * 64];
__device__ __align__(128) float g_dinv[MAXN];
__device__ __align__(128) int   g_degi[MAXN];
__device__ __align__(128) int   g_rowptr[MAXN + 1];
__device__ __align__(128) int   g_cursor[MAXN];
__device__ __align__(128) int   g_partials[64];
__device__ __align__(128) int   g_esrc[MAXE];
__device__ __align__(128) float g_enorm[MAXE];

// ---------------- helpers --------------------------------------------------
__device__ __forceinline__ float gelu_exact(float x) {
    return 0.5f * x * (1.0f + erff(x * 0.70710678118654752440f));
}
__device__ __forceinline__ uint32_t f2tf(float f) {
    uint32_t u;
    asm("cvt.rna.tf32.f32 %0, %1;" : "=r"(u) : "f"(f));
    return u;
}
__device__ __forceinline__ void mma_tf32(float* c, const uint32_t* a, const uint32_t* b) {
    asm("mma.sync.aligned.m16n8k8.row.col.f32.tf32.tf32.f32 "
        "{%0,%1,%2,%3},{%4,%5,%6,%7},{%8,%9},{%0,%1,%2,%3};"
        : "+f"(c[0]), "+f"(c[1]), "+f"(c[2]), "+f"(c[3])
        : "r"(a[0]), "r"(a[1]), "r"(a[2]), "r"(a[3]), "r"(b[0]), "r"(b[1]));
}

// ---------------- preprocessing: degree, dinv, CSR-by-dst ------------------
__global__ void k_count(int* deg, const int* __restrict__ dst, int e) {
    int i = blockIdx.x * blockDim.x + threadIdx.x;
    if (i < e) atomicAdd(&deg[dst[i]], 1);
}
__global__ void k_dinv(float* __restrict__ dinv, const int* __restrict__ deg, int n) {
    int i = blockIdx.x * blockDim.x + threadIdx.x;
    if (i < n) dinv[i] = rsqrtf((float)deg[i] + 1.0f);
}
__global__ void k_scan1(const int* __restrict__ deg, int* __restrict__ rowptr,
                        int* __restrict__ partials, int n) {
    __shared__ int sh[1024];
    int i = blockIdx.x * 1024 + threadIdx.x;
    int v = (i < n) ? deg[i] : 0;
    sh[threadIdx.x] = v;
    __syncthreads();
    #pragma unroll
    for (int o = 1; o < 1024; o <<= 1) {
        int t = (threadIdx.x >= o) ? sh[threadIdx.x - o] : 0;
        __syncthreads();
        sh[threadIdx.x] += t;
        __syncthreads();
    }
    int incl = sh[threadIdx.x];
    if (i < n) rowptr[i] = incl - v;              // exclusive within block
    if (threadIdx.x == 1023) partials[blockIdx.x] = incl;
}
__global__ void k_scan2(int* partials, int nblk) {
    if (threadIdx.x == 0) {
        int run = 0;
        for (int i = 0; i < nblk; i++) { int t = partials[i]; partials[i] = run; run += t; }
    }
}
__global__ void k_scan3(int* __restrict__ rowptr, int* __restrict__ cursor,
                        const int* __restrict__ partials, int n, int e) {
    int i = blockIdx.x * 1024 + threadIdx.x;
    if (i < n) {
        int v = rowptr[i] + partials[blockIdx.x];
        rowptr[i] = v;
        cursor[i] = v;
    }
    if (i == 0) rowptr[n] = e;
}
__global__ void k_bucket(const int* __restrict__ src, const int* __restrict__ dst,
                         const float* __restrict__ dinv, int* __restrict__ cursor,
                         int* __restrict__ esrc, float* __restrict__ enorm, int e) {
    int i = blockIdx.x * blockDim.x + threadIdx.x;
    if (i < e) {
        int s = src[i], d = dst[i];
        int pos = atomicAdd(&cursor[d], 1);
        esrc[pos] = s;
        enorm[pos] = dinv[s] * dinv[d];
    }
}

// ---------------- TF32 tensor-core GEMM ------------------------------------
// C[M,N] = A[M,K] @ B[K,N]; K%32==0, N%64==0, M bounds-checked.
// BM=128, BN=64, BK=32; 8 warps (4 in M x 2 in N); warp tile 32x32.
// MODE: 0 = raw store, 1 = +bias+addmat, 2 = gelu(x+bias)
template <int MODE>
__global__ void __launch_bounds__(256) sgemm_tc(
    const float* __restrict__ A, const float* __restrict__ B, float* __restrict__ C,
    int M, int K, int N, const float* __restrict__ bias, const float* __restrict__ add) {
    __shared__ uint32_t As[128][36];  // pitch 36: conflict-free STS.128 + LDS
    __shared__ uint32_t Bs[32][72];   // pitch 72: conflict-free STS.128 + LDS

    const int tid  = threadIdx.x;
    const int lane = tid & 31;
    const int wid  = tid >> 5;
    const int wm = wid & 3, wn = wid >> 2;
    const int gid = lane >> 2, tig = lane & 3;
    const int row0 = blockIdx.y * 128;
    const int col0 = blockIdx.x * 64;

    float acc[2][4][4];
    #pragma unroll
    for (int i = 0; i < 2; i++)
        #pragma unroll
        for (int j = 0; j < 4; j++)
            #pragma unroll
            for (int k = 0; k < 4; k++) acc[i][j][k] = 0.0f;

    for (int k0 = 0; k0 < K; k0 += 32) {
        #pragma unroll
        for (int i = 0; i < 4; i++) {
            int q = tid + i * 256;
            int row = q >> 3, kq = q & 7;
            float4 v = make_float4(0.f, 0.f, 0.f, 0.f);
            if (row0 + row < M)
                v = *(const float4*)&A[(size_t)(row0 + row) * K + k0 + kq * 4];
            uint4 u = make_uint4(f2tf(v.x), f2tf(v.y), f2tf(v.z), f2tf(v.w));
            *(uint4*)&As[row][kq * 4] = u;
        }
        #pragma unroll
        for (int i = 0; i < 2; i++) {
            int q = tid + i * 256;
            int kr = q >> 4, nq = q & 15;
            float4 v = *(const float4*)&B[(size_t)(k0 + kr) * N + col0 + nq * 4];
            uint4 u = make_uint4(f2tf(v.x), f2tf(v.y), f2tf(v.z), f2tf(v.w));
            *(uint4*)&Bs[kr][nq * 4] = u;
        }
        __syncthreads();

        #pragma unroll
        for (int kb = 0; kb < 32; kb += 8) {
            uint32_t af[2][4], bf[4][2];
            #pragma unroll
            for (int mt = 0; mt < 2; mt++) {
                int r = wm * 32 + mt * 16 + gid;
                af[mt][0] = As[r][kb + tig];
                af[mt][1] = As[r + 8][kb + tig];
                af[mt][2] = As[r][kb + tig + 4];
                af[mt][3] = As[r + 8][kb + tig + 4];
            }
            #pragma unroll
            for (int nt = 0; nt < 4; nt++) {
                int n = wn * 32 + nt * 8 + gid;
                bf[nt][0] = Bs[kb + tig][n];
                bf[nt][1] = Bs[kb + tig + 4][n];
            }
            #pragma unroll
            for (int mt = 0; mt < 2; mt++)
                #pragma unroll
                for (int nt = 0; nt < 4; nt++)
                    mma_tf32(acc[mt][nt], af[mt], bf[nt]);
        }
        __syncthreads();
    }

    // epilogue
    #pragma unroll
    for (int mt = 0; mt < 2; mt++) {
        #pragma unroll
        for (int half = 0; half < 2; half++) {
            int row = row0 + wm * 32 + mt * 16 + gid + half * 8;
            if (row >= M) continue;
            #pragma unroll
            for (int nt = 0; nt < 4; nt++) {
                int col = col0 + wn * 32 + nt * 8 + tig * 2;
                float v0 = acc[mt][nt][half * 2 + 0];
                float v1 = acc[mt][nt][half * 2 + 1];
                size_t o = (size_t)row * N + col;
                if (MODE == 1) {
                    v0 += bias[col]     + add[o];
                    v1 += bias[col + 1] + add[o + 1];
                } else if (MODE == 2) {
                    v0 = gelu_exact(v0 + bias[col]);
                    v1 = gelu_exact(v1 + bias[col + 1]);
                }
                *(float2*)&C[o] = make_float2(v0, v1);
            }
        }
    }
}

// ---------------- fused gather + conv-epilogue + LN + GELU -----------------
// One 256-thread block per node (C=256). agg stays in registers.
__global__ void __launch_bounds__(256) gcn_post(
    const float* __restrict__ hw, const float* __restrict__ pp,
    const int* __restrict__ rowptr, const int* __restrict__ esrc,
    const float* __restrict__ enorm, const float* __restrict__ dinv,
    const float* __restrict__ bcv, const float* __restrict__ bpv,
    const float* __restrict__ gv, const float* __restrict__ bev,
    float* __restrict__ skip_out, float* __restrict__ h_out) {
    int r = blockIdx.x;
    int c = threadIdx.x;
    int beg = rowptr[r], end = rowptr[r + 1];

    float acc = 0.0f;
    int j = beg;
    for (; j + 4 <= end; j += 4) {
        int s0 = esrc[j], s1 = esrc[j + 1], s2 = esrc[j + 2], s3 = esrc[j + 3];
        float w0 = enorm[j], w1 = enorm[j + 1], w2 = enorm[j + 2], w3 = enorm[j + 3];
        float v0 = hw[(size_t)s0 * 256 + c];
        float v1 = hw[(size_t)s1 * 256 + c];
        float v2 = hw[(size_t)s2 * 256 + c];
        float v3 = hw[(size_t)s3 * 256 + c];
        acc += v0 * w0;
        acc += v1 * w1;
        acc += v2 * w2;
        acc += v3 * w3;
    }
    for (; j < end; j++) acc += hw[(size_t)esrc[j] * 256 + c] * enorm[j];

    size_t idx = (size_t)r * 256 + c;
    float di = dinv[r];
    float t = acc + di * di * hw[idx] + bcv[c] + pp[idx] + bpv[c];
    skip_out[idx] = t;

    __shared__ float red[8];
    float s = t;
    #pragma unroll
    for (int o = 16; o > 0; o >>= 1) s += __shfl_xor_sync(0xffffffffu, s, o);
    if ((c & 31) == 0) red[c >> 5] = s;
    __syncthreads();
    float m = 0.f;
    #pragma unroll
    for (int i = 0; i < 8; i++) m += red[i];
    m *= (1.0f / 256.0f);
    __syncthreads();

    float d = t - m;
    float sq = d * d;
    #pragma unroll
    for (int o = 16; o > 0; o >>= 1) sq += __shfl_xor_sync(0xffffffffu, sq, o);
    if ((c & 31) == 0) red[c >> 5] = sq;
    __syncthreads();
    float v = 0.f;
    #pragma unroll
    for (int i = 0; i < 8; i++) v += red[i];
    v *= (1.0f / 256.0f);

    float y = d * rsqrtf(v + 1e-5f) * gv[c] + bev[c];
    h_out[idx] = gelu_exact(y);
}

// ---------------- log-softmax over 64 logits -------------------------------
__global__ void k_logsoftmax(const float* __restrict__ logits, const float* __restrict__ bf2,
                             float* __restrict__ out, int Nn) {
    int r = blockIdx.x * 8 + (threadIdx.x >> 5);
    int lane = threadIdx.x & 31;
    if (r >= Nn) return;
    float v0 = logits[(size_t)r * 64 + lane]      + bf2[lane];
    float v1 = logits[(size_t)r * 64 + 32 + lane] + bf2[32 + lane];
    float mx = fmaxf(v0, v1);
    #pragma unroll
    for (int o = 16; o > 0; o >>= 1) mx = fmaxf(mx, __shfl_xor_sync(0xffffffffu, mx, o));
    float s = expf(v0 - mx) + expf(v1 - mx);
    #pragma unroll
    for (int o = 16; o > 0; o >>= 1) s += __shfl_xor_sync(0xffffffffu, s, o);
    float ls = logf(s);
    out[(size_t)r * 64 + lane]      = v0 - mx - ls;
    out[(size_t)r * 64 + 32 + lane] = v1 - mx - ls;
}

// ---------------- launch ---------------------------------------------------
extern "C" void kernel_launch(void* const* d_in, const int* in_sizes, int n_in,
                              void* d_out, int out_size) {
    const float* x  = (const float*)d_in[0];
    const int*   ei = (const int*)d_in[1];
    int E  = in_sizes[1] / 2;
    int Nn = in_sizes[0] / 128;
    const int* src = ei;
    const int* dst = ei + E;

    const float* Wc[3] = {(const float*)d_in[2],  (const float*)d_in[8],  (const float*)d_in[14]};
    const float* bc[3] = {(const float*)d_in[3],  (const float*)d_in[9],  (const float*)d_in[15]};
    const float* Wp[3] = {(const float*)d_in[4],  (const float*)d_in[10], (const float*)d_in[16]};
    const float* bp[3] = {(const float*)d_in[5],  (const float*)d_in[11], (const float*)d_in[17]};
    const float* gg[3] = {(const float*)d_in[6],  (const float*)d_in[12], (const float*)d_in[18]};
    const float* be[3] = {(const float*)d_in[7],  (const float*)d_in[13], (const float*)d_in[19]};
    const float* W_in = (const float*)d_in[20];
    const float* b_in = (const float*)d_in[21];
    const float* Wf1  = (const float*)d_in[22];
    const float* bf1  = (const float*)d_in[23];
    const float* Wf2  = (const float*)d_in[24];
    const float* bf2  = (const float*)d_in[25];
    float* out = (float*)d_out;

    float *pH, *pSkip, *pHw, *pP, *pF1, *pLog, *pDinv, *pEn;
    int *pDegi, *pRp, *pCur, *pPart, *pEs;
    cudaGetSymbolAddress((void**)&pH,    g_h);
    cudaGetSymbolAddress((void**)&pSkip, g_skip);
    cudaGetSymbolAddress((void**)&pHw,   g_hw);
    cudaGetSymbolAddress((void**)&pP,    g_p);
    cudaGetSymbolAddress((void**)&pF1,   g_f1);
    cudaGetSymbolAddress((void**)&pLog,  g_logits);
    cudaGetSymbolAddress((void**)&pDinv, g_dinv);
    cudaGetSymbolAddress((void**)&pDegi, g_degi);
    cudaGetSymbolAddress((void**)&pRp,   g_rowptr);
    cudaGetSymbolAddress((void**)&pCur,  g_cursor);
    cudaGetSymbolAddress((void**)&pPart, g_partials);
    cudaGetSymbolAddress((void**)&pEs,   g_esrc);
    cudaGetSymbolAddress((void**)&pEn,   g_enorm);

    // --- preprocessing: degree, dinv, CSR buckets ---
    cudaMemsetAsync(pDegi, 0, (size_t)Nn * sizeof(int), 0);
    k_count<<<(E + 255) / 256, 256>>>(pDegi, dst, E);
    k_dinv <<<(Nn + 255) / 256, 256>>>(pDinv, pDegi, Nn);
    int nblk = (Nn + 1023) / 1024;
    k_scan1<<<nblk, 1024>>>(pDegi, pRp, pPart, Nn);
    k_scan2<<<1, 32>>>(pPart, nblk);
    k_scan3<<<nblk, 1024>>>(pRp, pCur, pPart, Nn, E);
    k_bucket<<<(E + 255) / 256, 256>>>(src, dst, pDinv, pCur, pEs, pEn, E);

    // --- 3 GCN layers ---
    const float* h    = x;
    const float* skip = x;
    int Kin = 128;
    int gy = (Nn + 127) / 128;
    for (int l = 0; l < 3; l++) {
        sgemm_tc<0><<<dim3(4, gy), 256>>>(h,    Wc[l], pHw, Nn, Kin, 256, nullptr, nullptr);
        sgemm_tc<0><<<dim3(4, gy), 256>>>(skip, Wp[l], pP,  Nn, Kin, 256, nullptr, nullptr);
        gcn_post<<<Nn, 256>>>(pHw, pP, pRp, pEs, pEn, pDinv,
                              bc[l], bp[l], gg[l], be[l], pSkip, pH);
        h = pH; skip = pSkip; Kin = 256;
    }

    // --- long residual (fused epilogue) + MLP head ---
    sgemm_tc<1><<<dim3(4, gy), 256>>>(x, W_in, pHw, Nn, 128, 256, b_in, pH);
    sgemm_tc<2><<<dim3(8, gy), 256>>>(pHw, Wf1, pF1, Nn, 256, 512, bf1, nullptr);
    sgemm_tc<0><<<dim3(1, gy), 256>>>(pF1, Wf2, pLog, Nn, 512, 64, nullptr, nullptr);
    k_logsoftmax<<<(Nn + 7) / 8, 256>>>(pLog, bf2, out, Nn);
}

// round 6
// speedup vs baseline: 2.3031x; 1.1222x over previous
#include <cuda_runtime.h>
#include <math.h>
#include <stdint.h>

#define MAXN 50048
#define MAXE 800000

// ---------------- scratch (device globals; no allocation allowed) ----------
__device__ __align__(128) float g_h[MAXN * 256];
__device__ __align__(128) float g_skip[MAXN * 256];
__device__ __align__(128) float g_hw[MAXN * 256];
__device__ __align__(128) float g_p[MAXN * 256];
__device__ __align__(128) float g_f1[MAXN * 512];
__device__ __align__(128) float g_logits[MAXN * 64];
__device__ __align__(128) float g_dinv[MAXN];
__device__ __align__(128) int   g_degi[MAXN];
__device__ __align__(128) int   g_rowptr[MAXN + 1];
__device__ __align__(128) int   g_cursor[MAXN];
__device__ __align__(128) int   g_partials[64];
__device__ __align__(128) int   g_esrc[MAXE];
__device__ __align__(128) float g_enorm[MAXE];

// ---------------- helpers --------------------------------------------------
__device__ __forceinline__ float gelu_exact(float x) {
    return 0.5f * x * (1.0f + erff(x * 0.70710678118654752440f));
}
__device__ __forceinline__ void mma_tf32(float* c, const uint32_t* a, const uint32_t* b) {
    asm("mma.sync.aligned.m16n8k8.row.col.f32.tf32.tf32.f32 "
        "{%0,%1,%2,%3},{%4,%5,%6,%7},{%8,%9},{%0,%1,%2,%3};"
        : "+f"(c[0]), "+f"(c[1]), "+f"(c[2]), "+f"(c[3])
        : "r"(a[0]), "r"(a[1]), "r"(a[2]), "r"(a[3]), "r"(b[0]), "r"(b[1]));
}
__device__ __forceinline__ void cp16(void* dst, const void* src, int bytes) {
    uint32_t d = (uint32_t)__cvta_generic_to_shared(dst);
    asm volatile("cp.async.cg.shared.global [%0], [%1], 16, %2;"
                 :: "r"(d), "l"(src), "r"(bytes));
}
__device__ __forceinline__ void cp_commit() { asm volatile("cp.async.commit_group;"); }
template <int N>
__device__ __forceinline__ void cp_wait() { asm volatile("cp.async.wait_group %0;" :: "n"(N)); }

// ---------------- preprocessing: degree, dinv, CSR-by-dst ------------------
__global__ void k_count(int* deg, const int* __restrict__ dst, int e) {
    int i = blockIdx.x * blockDim.x + threadIdx.x;
    if (i < e) atomicAdd(&deg[dst[i]], 1);
}
__global__ void k_dinv(float* __restrict__ dinv, const int* __restrict__ deg, int n) {
    int i = blockIdx.x * blockDim.x + threadIdx.x;
    if (i < n) dinv[i] = rsqrtf((float)deg[i] + 1.0f);
}
__global__ void k_scan1(const int* __restrict__ deg, int* __restrict__ rowptr,
                        int* __restrict__ partials, int n) {
    __shared__ int sh[1024];
    int i = blockIdx.x * 1024 + threadIdx.x;
    int v = (i < n) ? deg[i] : 0;
    sh[threadIdx.x] = v;
    __syncthreads();
    #pragma unroll
    for (int o = 1; o < 1024; o <<= 1) {
        int t = (threadIdx.x >= o) ? sh[threadIdx.x - o] : 0;
        __syncthreads();
        sh[threadIdx.x] += t;
        __syncthreads();
    }
    int incl = sh[threadIdx.x];
    if (i < n) rowptr[i] = incl - v;
    if (threadIdx.x == 1023) partials[blockIdx.x] = incl;
}
__global__ void k_scan2(int* partials, int nblk) {
    if (threadIdx.x == 0) {
        int run = 0;
        for (int i = 0; i < nblk; i++) { int t = partials[i]; partials[i] = run; run += t; }
    }
}
__global__ void k_scan3(int* __restrict__ rowptr, int* __restrict__ cursor,
                        const int* __restrict__ partials, int n, int e) {
    int i = blockIdx.x * 1024 + threadIdx.x;
    if (i < n) {
        int v = rowptr[i] + partials[blockIdx.x];
        rowptr[i] = v;
        cursor[i] = v;
    }
    if (i == 0) rowptr[n] = e;
}
__global__ void k_bucket(const int* __restrict__ src, const int* __restrict__ dst,
                         const float* __restrict__ dinv, int* __restrict__ cursor,
                         int* __restrict__ esrc, float* __restrict__ enorm, int e) {
    int i = blockIdx.x * blockDim.x + threadIdx.x;
    if (i < e) {
        int s = src[i], d = dst[i];
        int pos = atomicAdd(&cursor[d], 1);
        esrc[pos] = s;
        enorm[pos] = dinv[s] * dinv[d];
    }
}

// ---------------- TF32 tensor-core GEMM, 3-stage cp.async pipeline ---------
// C[M,N] = A[M,K] @ B[K,N]; K%32==0, N%64==0, M bounds-checked.
// BM=128, BN=64, BK=32, STAGES=3; 8 warps (4 in M x 2 in N), warp tile 32x32.
// fp32 fed raw to HMMA.tf32 (HW truncates mantissa -> RZ tf32).
// Stage buffers live in DYNAMIC shared memory (82944 B > 48 KB static limit).
// MODE: 0 = raw store, 1 = +bias+addmat, 2 = gelu(x+bias)
#define STAGES 3
#define A_PITCH 36
#define B_PITCH 72
#define A_STAGE (128 * A_PITCH)          // floats per A stage
#define B_STAGE (32 * B_PITCH)           // floats per B stage
#define SMEM_FLOATS (STAGES * (A_STAGE + B_STAGE))
#define SMEM_BYTES  (SMEM_FLOATS * 4)    // 82944

template <int MODE>
__global__ void __launch_bounds__(256) sgemm_tc(
    const float* __restrict__ A, const float* __restrict__ B, float* __restrict__ C,
    int M, int K, int N, const float* __restrict__ bias, const float* __restrict__ add) {
    extern __shared__ float smem[];
    float* As = smem;                          // [STAGES][128][A_PITCH]
    float* Bs = smem + STAGES * A_STAGE;       // [STAGES][32][B_PITCH]

    const int tid  = threadIdx.x;
    const int lane = tid & 31;
    const int wid  = tid >> 5;
    const int wm = wid & 3, wn = wid >> 2;
    const int gid = lane >> 2, tig = lane & 3;
    const int row0 = blockIdx.y * 128;
    const int col0 = blockIdx.x * 64;

    // per-thread load coordinates
    const int ar[4] = {(tid + 0) >> 3, (tid + 256) >> 3, (tid + 512) >> 3, (tid + 768) >> 3};
    const int ak = (tid & 7) * 4;
    const int br[2] = {(tid + 0) >> 4, (tid + 256) >> 4};
    const int bn = (tid & 15) * 4;

    const int k_tiles = K >> 5;

    auto load_stage = [&](int s, int k0) {
        float* as = As + s * A_STAGE;
        float* bs = Bs + s * B_STAGE;
        #pragma unroll
        for (int i = 0; i < 4; i++) {
            int row = ar[i];
            int grow = row0 + row;
            int ok = (grow < M) ? 16 : 0;
            if (!ok) grow = M - 1;  // keep address in-bounds
            cp16(&as[row * A_PITCH + ak], &A[(size_t)grow * K + k0 + ak], ok);
        }
        #pragma unroll
        for (int i = 0; i < 2; i++) {
            int kr = br[i];
            cp16(&bs[kr * B_PITCH + bn], &B[(size_t)(k0 + kr) * N + col0 + bn], 16);
        }
    };

    float acc[2][4][4];
    #pragma unroll
    for (int i = 0; i < 2; i++)
        #pragma unroll
        for (int j = 0; j < 4; j++)
            #pragma unroll
            for (int k = 0; k < 4; k++) acc[i][j][k] = 0.0f;

    // prologue: prefetch STAGES-1 stages
    #pragma unroll
    for (int s = 0; s < STAGES - 1; s++) {
        if (s < k_tiles) load_stage(s, s * 32);
        cp_commit();
    }

    for (int t = 0; t < k_tiles; t++) {
        cp_wait<STAGES - 2>();
        __syncthreads();
        const int st = t % STAGES;
        const float* as = As + st * A_STAGE;
        const float* bs = Bs + st * B_STAGE;

        #pragma unroll
        for (int kb = 0; kb < 32; kb += 8) {
            uint32_t af[2][4], bf[4][2];
            #pragma unroll
            for (int mt = 0; mt < 2; mt++) {
                int r = wm * 32 + mt * 16 + gid;
                af[mt][0] = __float_as_uint(as[r * A_PITCH + kb + tig]);
                af[mt][1] = __float_as_uint(as[(r + 8) * A_PITCH + kb + tig]);
                af[mt][2] = __float_as_uint(as[r * A_PITCH + kb + tig + 4]);
                af[mt][3] = __float_as_uint(as[(r + 8) * A_PITCH + kb + tig + 4]);
            }
            #pragma unroll
            for (int nt = 0; nt < 4; nt++) {
                int n = wn * 32 + nt * 8 + gid;
                bf[nt][0] = __float_as_uint(bs[(kb + tig) * B_PITCH + n]);
                bf[nt][1] = __float_as_uint(bs[(kb + tig + 4) * B_PITCH + n]);
            }
            #pragma unroll
            for (int mt = 0; mt < 2; mt++)
                #pragma unroll
                for (int nt = 0; nt < 4; nt++)
                    mma_tf32(acc[mt][nt], af[mt], bf[nt]);
        }

        int nt2 = t + STAGES - 1;
        if (nt2 < k_tiles) load_stage(nt2 % STAGES, nt2 * 32);
        cp_commit();
    }

    // epilogue
    #pragma unroll
    for (int mt = 0; mt < 2; mt++) {
        #pragma unroll
        for (int half = 0; half < 2; half++) {
            int row = row0 + wm * 32 + mt * 16 + gid + half * 8;
            if (row >= M) continue;
            #pragma unroll
            for (int nt = 0; nt < 4; nt++) {
                int col = col0 + wn * 32 + nt * 8 + tig * 2;
                float v0 = acc[mt][nt][half * 2 + 0];
                float v1 = acc[mt][nt][half * 2 + 1];
                size_t o = (size_t)row * N + col;
                if (MODE == 1) {
                    v0 += bias[col]     + add[o];
                    v1 += bias[col + 1] + add[o + 1];
                } else if (MODE == 2) {
                    v0 = gelu_exact(v0 + bias[col]);
                    v1 = gelu_exact(v1 + bias[col + 1]);
                }
                *(float2*)&C[o] = make_float2(v0, v1);
            }
        }
    }
}

// ---------------- fused gather + conv-epilogue + LN + GELU -----------------
// One 256-thread block per node (C=256). Edge lists staged through smem.
__global__ void __launch_bounds__(256) gcn_post(
    const float* __restrict__ hw, const float* __restrict__ pp,
    const int* __restrict__ rowptr, const int* __restrict__ esrc,
    const float* __restrict__ enorm, const float* __restrict__ dinv,
    const float* __restrict__ bcv, const float* __restrict__ bpv,
    const float* __restrict__ gv, const float* __restrict__ bev,
    float* __restrict__ skip_out, float* __restrict__ h_out) {
    int r = blockIdx.x;
    int c = threadIdx.x;
    int beg = rowptr[r], end = rowptr[r + 1];

    __shared__ int   sidx[128];
    __shared__ float swt[128];

    float acc = 0.0f;
    for (int chunk = beg; chunk < end; chunk += 128) {
        int cnt = min(128, end - chunk);
        if (c < cnt) {
            sidx[c] = esrc[chunk + c];
            swt[c]  = enorm[chunk + c];
        }
        __syncthreads();
        int j = 0;
        for (; j + 4 <= cnt; j += 4) {
            int   s0 = sidx[j],   s1 = sidx[j+1], s2 = sidx[j+2], s3 = sidx[j+3];
            float w0 = swt[j],    w1 = swt[j+1],  w2 = swt[j+2],  w3 = swt[j+3];
            float v0 = hw[(size_t)s0 * 256 + c];
            float v1 = hw[(size_t)s1 * 256 + c];
            float v2 = hw[(size_t)s2 * 256 + c];
            float v3 = hw[(size_t)s3 * 256 + c];
            acc += v0 * w0;
            acc += v1 * w1;
            acc += v2 * w2;
            acc += v3 * w3;
        }
        for (; j < cnt; j++) acc += hw[(size_t)sidx[j] * 256 + c] * swt[j];
        __syncthreads();
    }

    size_t idx = (size_t)r * 256 + c;
    float di = dinv[r];
    float t = acc + di * di * hw[idx] + bcv[c] + pp[idx] + bpv[c];
    skip_out[idx] = t;

    __shared__ float red[8];
    float s = t;
    #pragma unroll
    for (int o = 16; o > 0; o >>= 1) s += __shfl_xor_sync(0xffffffffu, s, o);
    if ((c & 31) == 0) red[c >> 5] = s;
    __syncthreads();
    float m = 0.f;
    #pragma unroll
    for (int i = 0; i < 8; i++) m += red[i];
    m *= (1.0f / 256.0f);
    __syncthreads();

    float d = t - m;
    float sq = d * d;
    #pragma unroll
    for (int o = 16; o > 0; o >>= 1) sq += __shfl_xor_sync(0xffffffffu, sq, o);
    if ((c & 31) == 0) red[c >> 5] = sq;
    __syncthreads();
    float v = 0.f;
    #pragma unroll
    for (int i = 0; i < 8; i++) v += red[i];
    v *= (1.0f / 256.0f);

    float y = d * rsqrtf(v + 1e-5f) * gv[c] + bev[c];
    h_out[idx] = gelu_exact(y);
}

// ---------------- log-softmax over 64 logits -------------------------------
__global__ void k_logsoftmax(const float* __restrict__ logits, const float* __restrict__ bf2,
                             float* __restrict__ out, int Nn) {
    int r = blockIdx.x * 8 + (threadIdx.x >> 5);
    int lane = threadIdx.x & 31;
    if (r >= Nn) return;
    float v0 = logits[(size_t)r * 64 + lane]      + bf2[lane];
    float v1 = logits[(size_t)r * 64 + 32 + lane] + bf2[32 + lane];
    float mx = fmaxf(v0, v1);
    #pragma unroll
    for (int o = 16; o > 0; o >>= 1) mx = fmaxf(mx, __shfl_xor_sync(0xffffffffu, mx, o));
    float s = expf(v0 - mx) + expf(v1 - mx);
    #pragma unroll
    for (int o = 16; o > 0; o >>= 1) s += __shfl_xor_sync(0xffffffffu, s, o);
    float ls = logf(s);
    out[(size_t)r * 64 + lane]      = v0 - mx - ls;
    out[(size_t)r * 64 + 32 + lane] = v1 - mx - ls;
}

// ---------------- launch ---------------------------------------------------
extern "C" void kernel_launch(void* const* d_in, const int* in_sizes, int n_in,
                              void* d_out, int out_size) {
    const float* x  = (const float*)d_in[0];
    const int*   ei = (const int*)d_in[1];
    int E  = in_sizes[1] / 2;
    int Nn = in_sizes[0] / 128;
    const int* src = ei;
    const int* dst = ei + E;

    const float* Wc[3] = {(const float*)d_in[2],  (const float*)d_in[8],  (const float*)d_in[14]};
    const float* bc[3] = {(const float*)d_in[3],  (const float*)d_in[9],  (const float*)d_in[15]};
    const float* Wp[3] = {(const float*)d_in[4],  (const float*)d_in[10], (const float*)d_in[16]};
    const float* bp[3] = {(const float*)d_in[5],  (const float*)d_in[11], (const float*)d_in[17]};
    const float* gg[3] = {(const float*)d_in[6],  (const float*)d_in[12], (const float*)d_in[18]};
    const float* be[3] = {(const float*)d_in[7],  (const float*)d_in[13], (const float*)d_in[19]};
    const float* W_in = (const float*)d_in[20];
    const float* b_in = (const float*)d_in[21];
    const float* Wf1  = (const float*)d_in[22];
    const float* bf1  = (const float*)d_in[23];
    const float* Wf2  = (const float*)d_in[24];
    const float* bf2  = (const float*)d_in[25];
    float* out = (float*)d_out;

    // opt in to >48KB dynamic smem (idempotent; called every time -- no static guards)
    cudaFuncSetAttribute(sgemm_tc<0>, cudaFuncAttributeMaxDynamicSharedMemorySize, SMEM_BYTES);
    cudaFuncSetAttribute(sgemm_tc<1>, cudaFuncAttributeMaxDynamicSharedMemorySize, SMEM_BYTES);
    cudaFuncSetAttribute(sgemm_tc<2>, cudaFuncAttributeMaxDynamicSharedMemorySize, SMEM_BYTES);

    float *pH, *pSkip, *pHw, *pP, *pF1, *pLog, *pDinv, *pEn;
    int *pDegi, *pRp, *pCur, *pPart, *pEs;
    cudaGetSymbolAddress((void**)&pH,    g_h);
    cudaGetSymbolAddress((void**)&pSkip, g_skip);
    cudaGetSymbolAddress((void**)&pHw,   g_hw);
    cudaGetSymbolAddress((void**)&pP,    g_p);
    cudaGetSymbolAddress((void**)&pF1,   g_f1);
    cudaGetSymbolAddress((void**)&pLog,  g_logits);
    cudaGetSymbolAddress((void**)&pDinv, g_dinv);
    cudaGetSymbolAddress((void**)&pDegi, g_degi);
    cudaGetSymbolAddress((void**)&pRp,   g_rowptr);
    cudaGetSymbolAddress((void**)&pCur,  g_cursor);
    cudaGetSymbolAddress((void**)&pPart, g_partials);
    cudaGetSymbolAddress((void**)&pEs,   g_esrc);
    cudaGetSymbolAddress((void**)&pEn,   g_enorm);

    // --- preprocessing ---
    cudaMemsetAsync(pDegi, 0, (size_t)Nn * sizeof(int), 0);
    k_count<<<(E + 255) / 256, 256>>>(pDegi, dst, E);
    k_dinv <<<(Nn + 255) / 256, 256>>>(pDinv, pDegi, Nn);
    int nblk = (Nn + 1023) / 1024;
    k_scan1<<<nblk, 1024>>>(pDegi, pRp, pPart, Nn);
    k_scan2<<<1, 32>>>(pPart, nblk);
    k_scan3<<<nblk, 1024>>>(pRp, pCur, pPart, Nn, E);
    k_bucket<<<(E + 255) / 256, 256>>>(src, dst, pDinv, pCur, pEs, pEn, E);

    // --- 3 GCN layers ---
    const float* h    = x;
    const float* skip = x;
    int Kin = 128;
    int gy = (Nn + 127) / 128;
    for (int l = 0; l < 3; l++) {
        sgemm_tc<0><<<dim3(4, gy), 256, SMEM_BYTES>>>(h,    Wc[l], pHw, Nn, Kin, 256, nullptr, nullptr);
        sgemm_tc<0><<<dim3(4, gy), 256, SMEM_BYTES>>>(skip, Wp[l], pP,  Nn, Kin, 256, nullptr, nullptr);
        gcn_post<<<Nn, 256>>>(pHw, pP, pRp, pEs, pEn, pDinv,
                              bc[l], bp[l], gg[l], be[l], pSkip, pH);
        h = pH; skip = pSkip; Kin = 256;
    }

    // --- long residual (fused epilogue) + MLP head ---
    sgemm_tc<1><<<dim3(4, gy), 256, SMEM_BYTES>>>(x, W_in, pHw, Nn, 128, 256, b_in, pH);
    sgemm_tc<2><<<dim3(8, gy), 256, SMEM_BYTES>>>(pHw, Wf1, pF1, Nn, 256, 512, bf1, nullptr);
    sgemm_tc<0><<<dim3(1, gy), 256, SMEM_BYTES>>>(pF1, Wf2, pLog, Nn, 512, 64, nullptr, nullptr);
    k_logsoftmax<<<(Nn + 7) / 8, 256>>>(pLog, bf2, out, Nn);
}